// round 4
// baseline (speedup 1.0000x reference)
#include <cuda_runtime.h>
#include <math.h>

#define B    16
#define P    2048
#define CIN  512
#define BP   (B*P)
#define NBK  64
#define JQ   4
#define K3_BLOCKS (BP/16)     // 2048 blocks, 16 rows each

// -------- device scratch --------
__device__ int    g_cnt[B][3];
__device__ int    g_idx[B][3];
__device__ float4 g_jbox[B][P];      // seeded j, bucket-sorted by x0
__device__ float4 g_jext[B][P];      // (area, mask0, mask1, mask2)
__device__ int    g_sjj[B][P];       // original j per sorted entry
__device__ float4 g_ibox[B][P];      // all i, bucket-sorted by x0
__device__ int    g_iori[B][P];      // original i per sorted rank
__device__ int    g_bst[B][NBK+1];   // bucket starts for seeded j list
__device__ float  g_maxw[B];
__device__ int    g_pr[JQ][B][3][P]; // per-quarter best keys
__device__ unsigned char g_ycls[BP];
__device__ float  g_w[BP];
__device__ int    g_imb[4];
__device__ unsigned long long g_loss_acc;
__device__ unsigned int g_tick;

// ============================================================
// K1: per (b,c) count(score>0.5) + first-argmax. grid = 48. Resets accums.
// ============================================================
__global__ void k1_seeds(const float* __restrict__ pre_score)
{
    int blk = blockIdx.x;
    int b = blk / 3, c = blk % 3;
    int t = threadIdx.x;
    __shared__ float s_max[256];
    __shared__ int   s_idx[256];
    __shared__ int   s_cnt[256];

    if (blk == 0) {
        if (t < 4) g_imb[t] = 0;
        if (t == 4) g_loss_acc = 0ULL;
        if (t == 5) g_tick = 0u;
    }

    const float4* sb = (const float4*)(pre_score + (size_t)b*P*4);
    float mv = -1e30f; int mi = P; int cnt = 0;
    for (int j = t; j < P; j += 256) {
        float4 v4 = sb[j];
        float v = (c == 0) ? v4.x : (c == 1) ? v4.y : v4.z;
        cnt += (v > 0.5f) ? 1 : 0;
        if (v > mv) { mv = v; mi = j; }
    }
    s_max[t] = mv; s_idx[t] = mi; s_cnt[t] = cnt;
    __syncthreads();
    for (int s = 128; s > 0; s >>= 1) {
        if (t < s) {
            float v2 = s_max[t+s]; int i2 = s_idx[t+s];
            if (v2 > s_max[t] || (v2 == s_max[t] && i2 < s_idx[t])) {
                s_max[t] = v2; s_idx[t] = i2;
            }
            s_cnt[t] += s_cnt[t+s];
        }
        __syncthreads();
    }
    if (t == 0) { g_cnt[b][c] = s_cnt[0]; g_idx[b][c] = s_idx[0]; }
}

// ============================================================
// K1b: per b — seed flags, x0 bucket histograms, stable scatter.
// ============================================================
__global__ void __launch_bounds__(256) k1b_build(
    const float* __restrict__ rois, const float* __restrict__ pre_score)
{
    __shared__ float4 sbx[P];
    __shared__ unsigned char sfl[P];
    __shared__ int hj[NBK], hi2[NBK];
    __shared__ int bsj[NBK+1], bsi[NBK+1];
    __shared__ int curj[NBK], curi[NBK];
    __shared__ float swm[8];
    __shared__ int th_cnt[3], th_idx[3];

    int b = blockIdx.x, t = threadIdx.x, lane = t & 31, warp = t >> 5;
    if (t < 3) { th_cnt[t] = g_cnt[b][t]; th_idx[t] = g_idx[b][t]; }
    if (t < NBK) { hj[t] = 0; hi2[t] = 0; }
    __syncthreads();

    const float4* rb = (const float4*)(rois      + (size_t)b*P*4);
    const float4* sb = (const float4*)(pre_score + (size_t)b*P*4);
    const float SCALE = NBK / 800.f;

    float wmax = 0.f;
    for (int j = t; j < P; j += 256) {
        float4 bx = rb[j];
        float4 sc = sb[j];
        int f0 = (th_cnt[0] <= 1) ? (j == th_idx[0]) : (sc.x > 0.5f);
        int f1 = (th_cnt[1] <= 1) ? (j == th_idx[1]) : (sc.y > 0.5f);
        int f2 = (th_cnt[2] <= 1) ? (j == th_idx[2]) : (sc.z > 0.5f);
        int fl = f0 | (f1 << 1) | (f2 << 2);
        sbx[j] = bx; sfl[j] = (unsigned char)fl;
        int bk = min(NBK-1, (int)(bx.x * SCALE));
        atomicAdd(&hi2[bk], 1);
        if (fl) { atomicAdd(&hj[bk], 1); wmax = fmaxf(wmax, bx.z - bx.x); }
    }
    for (int s = 16; s; s >>= 1) wmax = fmaxf(wmax, __shfl_xor_sync(~0u, wmax, s));
    if (lane == 0) swm[warp] = wmax;
    __syncthreads();
    if (t == 0) { float m = 0.f; for (int w2 = 0; w2 < 8; w2++) m = fmaxf(m, swm[w2]); g_maxw[b] = m; }

    if (warp < 2) {
        int* h  = warp ? hi2 : hj;
        int* bs = warp ? bsi : bsj;
        int a = h[lane], c = h[lane+32];
        int ia = a;
        #pragma unroll
        for (int s = 1; s < 32; s <<= 1) { int v = __shfl_up_sync(~0u, ia, s); if (lane >= s) ia += v; }
        int ta = __shfl_sync(~0u, ia, 31);
        int ic = c;
        #pragma unroll
        for (int s = 1; s < 32; s <<= 1) { int v = __shfl_up_sync(~0u, ic, s); if (lane >= s) ic += v; }
        int tc = __shfl_sync(~0u, ic, 31);
        bs[lane]    = ia - a;
        bs[lane+32] = ta + ic - c;
        if (lane == 31) bs[64] = ta + tc;
    }
    __syncthreads();
    if (t < NBK) { curj[t] = bsj[t]; curi[t] = bsi[t]; }
    if (t <= NBK) g_bst[b][t] = bsj[t];
    __syncthreads();

    if (warp == 0) {
        for (int base = 0; base < P; base += 32) {
            int j = base + lane;
            int fl = sfl[j];
            bool sel = fl != 0;
            float4 bx = sbx[j];
            int bk = sel ? min(NBK-1, (int)(bx.x * SCALE)) : (NBK + lane);
            unsigned grp = __match_any_sync(~0u, bk);
            int rank = __popc(grp & ((1u << lane) - 1));
            int ldr = __ffs(grp) - 1;
            int old = 0;
            if (sel && lane == ldr) { old = curj[bk]; curj[bk] = old + __popc(grp); }
            old = __shfl_sync(~0u, old, ldr);
            if (sel) {
                int pos = old + rank;
                g_jbox[b][pos] = bx;
                g_jext[b][pos] = make_float4((bx.z - bx.x) * (bx.w - bx.y),
                    __int_as_float((fl & 1) ? -1 : 0),
                    __int_as_float((fl & 2) ? -1 : 0),
                    __int_as_float((fl & 4) ? -1 : 0));
                g_sjj[b][pos] = j;
            }
            __syncwarp();
        }
    } else if (warp == 1) {
        for (int base = 0; base < P; base += 32) {
            int i = base + lane;
            float4 bx = sbx[i];
            int bk = min(NBK-1, (int)(bx.x * SCALE));
            unsigned grp = __match_any_sync(~0u, bk);
            int rank = __popc(grp & ((1u << lane) - 1));
            int ldr = __ffs(grp) - 1;
            int old = 0;
            if (lane == ldr) { old = curi[bk]; curi[bk] = old + __popc(grp); }
            old = __shfl_sync(~0u, old, ldr);
            int pos = old + rank;
            g_ibox[b][pos] = bx;
            g_iori[b][pos] = i;
            __syncwarp();
        }
    }
}

// ============================================================
// K2: spatially-culled seeded IoU argmax. 1024 blocks x 128 thr.
// ============================================================
__global__ void __launch_bounds__(128) k2_scan()
{
    __shared__ float4 sbox[512];
    __shared__ float4 sext[512];
    __shared__ int    sbs[NBK+1];
    __shared__ float  smw;

    int blk = blockIdx.x;
    int q = blk & 3, tile = (blk >> 2) & 15, b = blk >> 6;
    int t = threadIdx.x;
    const float SCALE = NBK / 800.f;

    for (int v = t; v <= NBK; v += 128) sbs[v] = g_bst[b][v];
    if (t == 0) smw = g_maxw[b];
    __syncthreads();

    int n = sbs[NBK];
    int chunk = (n + 3) >> 2;
    int base = q * chunk;
    int len = min(chunk, n - base); if (len < 0) len = 0;
    for (int k = t; k < len; k += 128) {
        sbox[k] = g_jbox[b][base + k];
        sext[k] = g_jext[b][base + k];
    }
    __syncthreads();

    int rank = tile * 128 + t;
    float4 bi = g_ibox[b][rank];
    float  ai = (bi.z - bi.x) * (bi.w - bi.y);

    float lox = bi.x - smw;
    int lob = max(0, (int)(lox * SCALE));
    int hib = min(NBK-1, (int)(bi.z * SCALE));
    // per-lane range, FULLY clamped into [base, base+len] BEFORE warp union
    int lo = min(max(sbs[lob], base), base + len);
    int hi = min(max(sbs[hib + 1], base), base + len);
    if (hi < lo) hi = lo;
    #pragma unroll
    for (int s = 16; s; s >>= 1) {
        lo = min(lo, __shfl_xor_sync(~0u, lo, s));
        hi = max(hi, __shfl_xor_sync(~0u, hi, s));
    }

    int K0 = 0, K1 = 0, K2v = 0;
    int kk = lo;
    #pragma unroll 4
    for (int k = lo - base; k < hi - base; k++, kk++) {
        float4 o = sbox[k];
        float4 e = sext[k];
        float ltx = fmaxf(bi.x, o.x);
        float lty = fmaxf(bi.y, o.y);
        float rbx = fminf(bi.z, o.z);
        float rby = fminf(bi.w, o.w);
        float wx  = fmaxf(rbx - ltx, 0.f);
        float wy  = fmaxf(rby - lty, 0.f);
        float inter = wx * wy;
        float den   = ai + e.x - inter;
        float rcp;
        asm("rcp.approx.f32 %0, %1;" : "=f"(rcp) : "f"(den));
        float r = inter * rcp;
        int key = (__float_as_int(r) & 0xFFFFF800) | kk;
        K0  = max(K0,  key & __float_as_int(e.y));
        K1  = max(K1,  key & __float_as_int(e.z));
        K2v = max(K2v, key & __float_as_int(e.w));
    }

    g_pr[q][b][0][rank] = K0;
    g_pr[q][b][1][rank] = K1;
    g_pr[q][b][2][rank] = K2v;
}

// ============================================================
// K_MERGE: combine 4 quarter keys, sequential class selection.
// ============================================================
__global__ void k_merge(const float* __restrict__ labels,
                        const float* __restrict__ pre_score)
{
    __shared__ int hist[4];
    int t = threadIdx.x;
    if (t < 4) hist[t] = 0;
    __syncthreads();

    int gr = blockIdx.x * 256 + t;
    int b = gr >> 11, rank = gr & 2047;
    int iorig = g_iori[b][rank];

    float Ibest = -1.f, wv = 1.f; int yc = 3;
    #pragma unroll
    for (int c = 0; c < 3; c++) {
        int key = g_pr[0][b][c][rank];
        key = max(key, g_pr[1][b][c][rank]);
        key = max(key, g_pr[2][b][c][rank]);
        key = max(key, g_pr[3][b][c][rank]);
        float rq = __int_as_float(key & 0xFFFFF800);
        bool upd = (labels[b*4 + c] > 0.f) && (rq >= 0.5f) && (rq > Ibest);
        if (upd) {
            int kidx = key & 0x7FF;
            int j = g_sjj[b][kidx];
            Ibest = rq;
            wv = pre_score[((b << 11) + j)*4 + c];
            yc = c;
        }
    }
    int row = (b << 11) + iorig;
    g_ycls[row] = (unsigned char)yc;
    g_w[row]    = wv;
    atomicAdd(&hist[yc], 1);
    __syncthreads();
    if (t < 4 && hist[t]) atomicAdd(&g_imb[t], hist[t]);
}

// ============================================================
// K3: GEMM + softmax + focal loss; 2 rows/warp.
// ============================================================
__global__ void __launch_bounds__(256) k3_loss(
    const float* __restrict__ inputs,
    const float* __restrict__ labels,
    const float* __restrict__ fcw,
    const float* __restrict__ fcb,
    float* __restrict__ out)
{
    __shared__ float4 wT[512];
    __shared__ float  sred[8];

    int t = threadIdx.x, warp = t >> 5, lane = t & 31;
    int row0 = blockIdx.x * 16 + warp * 2;

    const float4* xa = (const float4*)(inputs + (size_t)row0 * CIN);
    const float4* xb = (const float4*)(inputs + (size_t)(row0 + 1) * CIN);
    float4 ra[4], rb2[4];
    #pragma unroll
    for (int u = 0; u < 4; u++) { ra[u] = xa[lane + 32*u]; rb2[u] = xb[lane + 32*u]; }

    const float4* fw4 = (const float4*)fcw;
    for (int idx = t; idx < 512; idx += 256) wT[idx] = fw4[idx];
    __syncthreads();

    float a0=0,a1=0,a2=0,a3=0, b0=0,b1=0,b2=0,b3=0;
    #pragma unroll
    for (int u = 0; u < 4; u++) {
        int m = lane + 32*u;
        float4 w0 = wT[m], w1 = wT[128+m], w2 = wT[256+m], w3 = wT[384+m];
        float4 x = ra[u], y = rb2[u];
        a0 += x.x*w0.x + x.y*w0.y + x.z*w0.z + x.w*w0.w;
        a1 += x.x*w1.x + x.y*w1.y + x.z*w1.z + x.w*w1.w;
        a2 += x.x*w2.x + x.y*w2.y + x.z*w2.z + x.w*w2.w;
        a3 += x.x*w3.x + x.y*w3.y + x.z*w3.z + x.w*w3.w;
        b0 += y.x*w0.x + y.y*w0.y + y.z*w0.z + y.w*w0.w;
        b1 += y.x*w1.x + y.y*w1.y + y.z*w1.z + y.w*w1.w;
        b2 += y.x*w2.x + y.y*w2.y + y.z*w2.z + y.w*w2.w;
        b3 += y.x*w3.x + y.y*w3.y + y.z*w3.z + y.w*w3.w;
    }
    #pragma unroll
    for (int s = 16; s > 0; s >>= 1) {
        a0 += __shfl_xor_sync(~0u, a0, s); a1 += __shfl_xor_sync(~0u, a1, s);
        a2 += __shfl_xor_sync(~0u, a2, s); a3 += __shfl_xor_sync(~0u, a3, s);
        b0 += __shfl_xor_sync(~0u, b0, s); b1 += __shfl_xor_sync(~0u, b1, s);
        b2 += __shfl_xor_sync(~0u, b2, s); b3 += __shfl_xor_sync(~0u, b3, s);
    }

    if (lane == 0) {
        float contrib = 0.f;
        float bias0 = fcb[0], bias1 = fcb[1], bias2 = fcb[2], bias3 = fcb[3];
        #pragma unroll
        for (int rr = 0; rr < 2; rr++) {
            int row = row0 + rr;
            float xr0 = (rr ? b0 : a0) + bias0;
            float xr1 = (rr ? b1 : a1) + bias1;
            float xr2 = (rr ? b2 : a2) + bias2;
            float xr3 = (rr ? b3 : a3) + bias3;
            float mx = fmaxf(fmaxf(xr0, xr1), fmaxf(xr2, xr3));
            float e0 = expf(xr0 - mx), e1 = expf(xr1 - mx);
            float e2 = expf(xr2 - mx), e3 = expf(xr3 - mx);
            float inv = 1.f / (e0 + e1 + e2 + e3);
            float l0 = e0*inv, l1 = e1*inv, l2 = e2*inv, l3 = e3*inv;
            ((float4*)out)[row] = make_float4(l0, l1, l2, l3);

            int   bb = row >> 11;
            int   k  = (int)g_ycls[row];
            float lk = (k == 0) ? l0 : (k == 1) ? l1 : (k == 2) ? l2 : l3;
            float p  = fminf(fmaxf(lk, 1e-7f), 1.f - 1e-7f);
            float om = 1.f - p;
            float fl = -logf(p) * om * om;
            float imbk = (float)g_imb[k];
            float labk = (k == 3) ? 1.f : labels[bb*4 + k];
            float wbar = 10.f * expf(lk) * (1.f - labk) + labk;
            contrib += g_w[row] * fl / (imbk + 1e-7f) * wbar;
        }
        sred[warp] = contrib;
    }
    __syncthreads();
    if (t == 0) {
        double s = 0.0;
        #pragma unroll
        for (int wi = 0; wi < 8; wi++) s += (double)sred[wi];
        unsigned long long qv = (unsigned long long)__double2ll_rn(s * 4294967296.0);
        atomicAdd(&g_loss_acc, qv);
        __threadfence();
        unsigned tick = atomicAdd(&g_tick, 1u);
        if (tick == K3_BLOCKS - 1) {
            unsigned long long acc = atomicAdd(&g_loss_acc, 0ULL);
            out[BP*4] = (float)((double)acc * (1.0/4294967296.0) / (double)B);
        }
    }
}

// ============================================================
extern "C" void kernel_launch(void* const* d_in, const int* in_sizes, int n_in,
                              void* d_out, int out_size)
{
    const float* inputs    = (const float*)d_in[0];
    const float* pre_score = (const float*)d_in[1];
    const float* labels    = (const float*)d_in[2];
    const float* rois      = (const float*)d_in[3];
    const float* fcw       = (const float*)d_in[4];
    const float* fcb       = (const float*)d_in[5];
    float* out = (float*)d_out;

    k1_seeds<<<B*3, 256>>>(pre_score);
    k1b_build<<<B, 256>>>(rois, pre_score);
    k2_scan<<<B*16*JQ, 128>>>();
    k_merge<<<BP/256, 256>>>(labels, pre_score);
    k3_loss<<<K3_BLOCKS, 256>>>(inputs, labels, fcw, fcb, out);
}

// round 6
// speedup vs baseline: 1.0465x; 1.0465x over previous
#include <cuda_runtime.h>
#include <math.h>

#define B    16
#define P    2048
#define CIN  512
#define BP   (B*P)
#define NBK  64
#define K3_BLOCKS (BP/16)     // 2048 blocks, 16 rows each

// -------- device scratch --------
__device__ float4 g_jbox[B][P];      // seeded j boxes, bucket-sorted by x0
__device__ float4 g_jext[B][P];      // (area, m0, m1, m2) m = 0 or 0x7FFFFFFF
__device__ int    g_sjj[B][P];       // original j per sorted entry
__device__ float4 g_ibox[B][P];      // all i boxes, bucket-sorted by x0
__device__ int    g_iori[B][P];      // original i per sorted rank
__device__ int    g_bst[B][NBK+1];   // seeded-j bucket starts
__device__ float  g_maxw[B];
__device__ unsigned char g_ycls[BP];
__device__ float  g_w[BP];
__device__ int    g_imb[4];
__device__ unsigned long long g_loss_acc;
__device__ unsigned int g_tick;

// ============================================================
// K0: per-b — seed stats (count/argmax per class), flags, x0 bucket
// histograms, scans, stable parallel scatter. grid = B, 256 threads.
// ============================================================
__global__ void __launch_bounds__(256) k0_build(
    const float* __restrict__ rois, const float* __restrict__ pre_score)
{
    __shared__ float4 sbx[P];              // 32 KB
    __shared__ unsigned char sfl[P];       // 2 KB
    __shared__ float s_max[256];
    __shared__ int   s_idx[256], s_cnt[256];
    __shared__ int   th_cnt[3], th_idx[3];
    __shared__ int   hj[NBK], hi2[NBK];
    __shared__ int   bsj[NBK+1], bsi[NBK+1];
    __shared__ int   curj[NBK], curi[NBK];
    __shared__ float swm[8];

    int b = blockIdx.x, t = threadIdx.x, lane = t & 31, warp = t >> 5;
    if (b == 0) {
        if (t < 4) g_imb[t] = 0;
        if (t == 4) g_loss_acc = 0ULL;
        if (t == 5) g_tick = 0u;
    }
    if (t < NBK) { hj[t] = 0; hi2[t] = 0; }

    const float4* rb = (const float4*)(rois      + (size_t)b*P*4);
    const float4* sb = (const float4*)(pre_score + (size_t)b*P*4);
    const float SCALE = NBK / 800.f;

    // Phase A: per-class count(>0.5) + first-argmax; also stage boxes.
    float mv[3] = {-1e30f, -1e30f, -1e30f};
    int   mi[3] = {P, P, P};
    int   cn[3] = {0, 0, 0};
    for (int j = t; j < P; j += 256) {
        sbx[j] = rb[j];
        float4 s = sb[j];
        float v0 = s.x, v1 = s.y, v2 = s.z;
        cn[0] += (v0 > 0.5f); if (v0 > mv[0]) { mv[0] = v0; mi[0] = j; }
        cn[1] += (v1 > 0.5f); if (v1 > mv[1]) { mv[1] = v1; mi[1] = j; }
        cn[2] += (v2 > 0.5f); if (v2 > mv[2]) { mv[2] = v2; mi[2] = j; }
    }
    #pragma unroll
    for (int c = 0; c < 3; c++) {
        s_max[t] = mv[c]; s_idx[t] = mi[c]; s_cnt[t] = cn[c];
        __syncthreads();
        for (int s = 128; s > 0; s >>= 1) {
            if (t < s) {
                float v2 = s_max[t+s]; int i2 = s_idx[t+s];
                if (v2 > s_max[t] || (v2 == s_max[t] && i2 < s_idx[t])) {
                    s_max[t] = v2; s_idx[t] = i2;
                }
                s_cnt[t] += s_cnt[t+s];
            }
            __syncthreads();
        }
        if (t == 0) { th_cnt[c] = s_cnt[0]; th_idx[c] = s_idx[0]; }
        __syncthreads();
    }

    // Phase B: flags, histograms, max seeded width.
    float wmax = 0.f;
    for (int j = t; j < P; j += 256) {
        float4 bx = sbx[j];
        float4 sc = sb[j];
        int f0 = (th_cnt[0] <= 1) ? (j == th_idx[0]) : (sc.x > 0.5f);
        int f1 = (th_cnt[1] <= 1) ? (j == th_idx[1]) : (sc.y > 0.5f);
        int f2 = (th_cnt[2] <= 1) ? (j == th_idx[2]) : (sc.z > 0.5f);
        int fl = f0 | (f1 << 1) | (f2 << 2);
        sfl[j] = (unsigned char)fl;
        int bk = min(NBK-1, (int)(bx.x * SCALE));
        atomicAdd(&hi2[bk], 1);
        if (fl) { atomicAdd(&hj[bk], 1); wmax = fmaxf(wmax, bx.z - bx.x); }
    }
    for (int s = 16; s; s >>= 1) wmax = fmaxf(wmax, __shfl_xor_sync(~0u, wmax, s));
    if (lane == 0) swm[warp] = wmax;
    __syncthreads();
    if (t == 0) { float m = 0.f; for (int w2 = 0; w2 < 8; w2++) m = fmaxf(m, swm[w2]); g_maxw[b] = m; }

    // exclusive scans (warp0 -> bsj, warp1 -> bsi)
    if (warp < 2) {
        int* h  = warp ? hi2 : hj;
        int* bs = warp ? bsi : bsj;
        int a = h[lane], c = h[lane+32];
        int ia = a;
        #pragma unroll
        for (int s = 1; s < 32; s <<= 1) { int v = __shfl_up_sync(~0u, ia, s); if (lane >= s) ia += v; }
        int ta = __shfl_sync(~0u, ia, 31);
        int ic = c;
        #pragma unroll
        for (int s = 1; s < 32; s <<= 1) { int v = __shfl_up_sync(~0u, ic, s); if (lane >= s) ic += v; }
        int tc = __shfl_sync(~0u, ic, 31);
        bs[lane]    = ia - a;
        bs[lane+32] = ta + ic - c;
        if (lane == 31) bs[64] = ta + tc;
    }
    __syncthreads();
    if (t < NBK) { curj[t] = bsj[t]; curi[t] = bsi[t]; }
    if (t <= NBK) g_bst[b][t] = bsj[t];
    __syncthreads();

    // Stable parallel scatter: warps 0-3 own 16 j-buckets each; 4-7 own i-buckets.
    if (warp < 4) {
        for (int base = 0; base < P; base += 32) {
            int j = base + lane;
            int fl = sfl[j];
            float4 bx = sbx[j];
            int bk = fl ? min(NBK-1, (int)(bx.x * SCALE)) : 999;
            bool mine = fl && ((bk >> 4) == warp);
            unsigned key = mine ? (unsigned)bk : (64u + lane);
            unsigned grp = __match_any_sync(~0u, key);
            int rnk = __popc(grp & ((1u << lane) - 1));
            int ldr = __ffs(grp) - 1;
            int old = 0;
            if (mine && lane == ldr) { old = curj[bk]; curj[bk] = old + __popc(grp); }
            old = __shfl_sync(~0u, old, ldr);
            if (mine) {
                int pos = old + rnk;
                g_jbox[b][pos] = bx;
                g_jext[b][pos] = make_float4((bx.z - bx.x) * (bx.w - bx.y),
                    __int_as_float((fl & 1) ? 0x7FFFFFFF : 0),
                    __int_as_float((fl & 2) ? 0x7FFFFFFF : 0),
                    __int_as_float((fl & 4) ? 0x7FFFFFFF : 0));
                g_sjj[b][pos] = j;
            }
            __syncwarp();
        }
    } else {
        int wo = warp - 4;
        for (int base = 0; base < P; base += 32) {
            int i = base + lane;
            float4 bx = sbx[i];
            int bk = min(NBK-1, (int)(bx.x * SCALE));
            bool mine = (bk >> 4) == wo;
            unsigned key = mine ? (unsigned)bk : (64u + lane);
            unsigned grp = __match_any_sync(~0u, key);
            int rnk = __popc(grp & ((1u << lane) - 1));
            int ldr = __ffs(grp) - 1;
            int old = 0;
            if (mine && lane == ldr) { old = curi[bk]; curi[bk] = old + __popc(grp); }
            old = __shfl_sync(~0u, old, ldr);
            if (mine) {
                int pos = old + rnk;
                g_ibox[b][pos] = bx;
                g_iori[b][pos] = i;
            }
            __syncwarp();
        }
    }
}

// ============================================================
// K2: one block per (b, i-tile of 128 sorted i). Full seeded-j list in
// dynamic smem; per-warp culled window; writes FINAL ycls/w/imb.
// grid = 256 x 128 threads, 64KB dynamic smem.
// ============================================================
__global__ void __launch_bounds__(128) k2_scan(
    const float* __restrict__ pre_score, const float* __restrict__ labels)
{
    extern __shared__ char dsm[];
    float4* sbox = (float4*)dsm;               // 2048 * 16B
    float4* sext = (float4*)(dsm + P*16);      // 2048 * 16B
    __shared__ int   sbs[NBK+1];
    __shared__ float smw, slab[3];
    __shared__ int   hist[4];

    int blk = blockIdx.x;
    int b = blk >> 4, tile = blk & 15;
    int t = threadIdx.x;
    const float SCALE = NBK / 800.f;

    if (t < 4) hist[t] = 0;
    if (t < 3) slab[t] = labels[b*4 + t];
    for (int v = t; v <= NBK; v += 128) sbs[v] = g_bst[b][v];
    __syncthreads();
    if (t == 0) smw = g_maxw[b];
    int n = sbs[NBK];
    for (int k = t; k < n; k += 128) {
        sbox[k] = g_jbox[b][k];
        sext[k] = g_jext[b][k];
    }
    __syncthreads();

    int rank = tile * 128 + t;
    float4 bi = g_ibox[b][rank];
    float  ai = (bi.z - bi.x) * (bi.w - bi.y);

    float lox = bi.x - smw;
    int lob = max(0, (int)(lox * SCALE));
    int hib = min(NBK-1, (int)(bi.z * SCALE));
    int lo = sbs[lob], hi = sbs[hib + 1];
    if (hi < lo) hi = lo;
    #pragma unroll
    for (int s = 16; s; s >>= 1) {
        lo = min(lo, __shfl_xor_sync(~0u, lo, s));
        hi = max(hi, __shfl_xor_sync(~0u, hi, s));
    }

    int K0 = 0, K1 = 0, K2v = 0;
    #pragma unroll 4
    for (int k = lo; k < hi; k++) {
        float4 o = sbox[k];
        float4 e = sext[k];
        float ltx = fmaxf(bi.x, o.x);
        float lty = fmaxf(bi.y, o.y);
        float rbx = fminf(bi.z, o.z);
        float rby = fminf(bi.w, o.w);
        float wx  = fmaxf(rbx - ltx, 0.f);
        float wy  = fmaxf(rby - lty, 0.f);
        float inter = wx * wy;
        float den   = ai + e.x - inter;
        float rcp;
        asm("rcp.approx.f32 %0, %1;" : "=f"(rcp) : "f"(den));
        float r = inter * rcp;
        int key = (__float_as_int(r) & 0xFFFFF800) | k;   // one LOP3
        K0  = max(K0,  min(key, __float_as_int(e.y)));
        K1  = max(K1,  min(key, __float_as_int(e.z)));
        K2v = max(K2v, min(key, __float_as_int(e.w)));
    }

    // epilogue: sequential class selection, final outputs
    int iorig = g_iori[b][rank];
    float Ibest = -1.f, wv = 1.f; int yc = 3;
    int keys[3] = {K0, K1, K2v};
    #pragma unroll
    for (int c = 0; c < 3; c++) {
        int key = keys[c];
        float rq = __int_as_float(key & 0xFFFFF800);
        bool upd = (slab[c] > 0.f) && (rq >= 0.5f) && (rq > Ibest);
        if (upd) {
            int j = g_sjj[b][key & 0x7FF];
            Ibest = rq;
            wv = pre_score[((b << 11) + j)*4 + c];
            yc = c;
        }
    }
    int row = (b << 11) + iorig;
    g_ycls[row] = (unsigned char)yc;
    g_w[row]    = wv;
    atomicAdd(&hist[yc], 1);
    __syncthreads();
    if (t < 4 && hist[t]) atomicAdd(&g_imb[t], hist[t]);
}

// ============================================================
// K3: GEMM + softmax + focal loss; 2 rows/warp; fixed-point reduce.
// ============================================================
__global__ void __launch_bounds__(256) k3_loss(
    const float* __restrict__ inputs,
    const float* __restrict__ labels,
    const float* __restrict__ fcw,
    const float* __restrict__ fcb,
    float* __restrict__ out)
{
    __shared__ float4 wT[512];
    __shared__ float  sred[8];

    int t = threadIdx.x, warp = t >> 5, lane = t & 31;
    int row0 = blockIdx.x * 16 + warp * 2;

    const float4* xa = (const float4*)(inputs + (size_t)row0 * CIN);
    const float4* xb = (const float4*)(inputs + (size_t)(row0 + 1) * CIN);
    float4 ra[4], rb2[4];
    #pragma unroll
    for (int u = 0; u < 4; u++) { ra[u] = xa[lane + 32*u]; rb2[u] = xb[lane + 32*u]; }

    const float4* fw4 = (const float4*)fcw;
    for (int idx = t; idx < 512; idx += 256) wT[idx] = fw4[idx];
    __syncthreads();

    float a0=0,a1=0,a2=0,a3=0, b0=0,b1=0,b2=0,b3=0;
    #pragma unroll
    for (int u = 0; u < 4; u++) {
        int m = lane + 32*u;
        float4 w0 = wT[m], w1 = wT[128+m], w2 = wT[256+m], w3 = wT[384+m];
        float4 x = ra[u], y = rb2[u];
        a0 += x.x*w0.x + x.y*w0.y + x.z*w0.z + x.w*w0.w;
        a1 += x.x*w1.x + x.y*w1.y + x.z*w1.z + x.w*w1.w;
        a2 += x.x*w2.x + x.y*w2.y + x.z*w2.z + x.w*w2.w;
        a3 += x.x*w3.x + x.y*w3.y + x.z*w3.z + x.w*w3.w;
        b0 += y.x*w0.x + y.y*w0.y + y.z*w0.z + y.w*w0.w;
        b1 += y.x*w1.x + y.y*w1.y + y.z*w1.z + y.w*w1.w;
        b2 += y.x*w2.x + y.y*w2.y + y.z*w2.z + y.w*w2.w;
        b3 += y.x*w3.x + y.y*w3.y + y.z*w3.z + y.w*w3.w;
    }
    #pragma unroll
    for (int s = 16; s > 0; s >>= 1) {
        a0 += __shfl_xor_sync(~0u, a0, s); a1 += __shfl_xor_sync(~0u, a1, s);
        a2 += __shfl_xor_sync(~0u, a2, s); a3 += __shfl_xor_sync(~0u, a3, s);
        b0 += __shfl_xor_sync(~0u, b0, s); b1 += __shfl_xor_sync(~0u, b1, s);
        b2 += __shfl_xor_sync(~0u, b2, s); b3 += __shfl_xor_sync(~0u, b3, s);
    }

    if (lane == 0) {
        float contrib = 0.f;
        float bias0 = fcb[0], bias1 = fcb[1], bias2 = fcb[2], bias3 = fcb[3];
        #pragma unroll
        for (int rr = 0; rr < 2; rr++) {
            int row = row0 + rr;
            float xr0 = (rr ? b0 : a0) + bias0;
            float xr1 = (rr ? b1 : a1) + bias1;
            float xr2 = (rr ? b2 : a2) + bias2;
            float xr3 = (rr ? b3 : a3) + bias3;
            float mx = fmaxf(fmaxf(xr0, xr1), fmaxf(xr2, xr3));
            float e0 = expf(xr0 - mx), e1 = expf(xr1 - mx);
            float e2 = expf(xr2 - mx), e3 = expf(xr3 - mx);
            float inv = 1.f / (e0 + e1 + e2 + e3);
            float l0 = e0*inv, l1 = e1*inv, l2 = e2*inv, l3 = e3*inv;
            ((float4*)out)[row] = make_float4(l0, l1, l2, l3);

            int   bb = row >> 11;
            int   k  = (int)g_ycls[row];
            float lk = (k == 0) ? l0 : (k == 1) ? l1 : (k == 2) ? l2 : l3;
            float p  = fminf(fmaxf(lk, 1e-7f), 1.f - 1e-7f);
            float om = 1.f - p;
            float fl = -logf(p) * om * om;
            float imbk = (float)g_imb[k];
            float labk = (k == 3) ? 1.f : labels[bb*4 + k];
            float wbar = 10.f * expf(lk) * (1.f - labk) + labk;
            contrib += g_w[row] * fl / (imbk + 1e-7f) * wbar;
        }
        sred[warp] = contrib;
    }
    __syncthreads();
    if (t == 0) {
        double s = 0.0;
        #pragma unroll
        for (int wi = 0; wi < 8; wi++) s += (double)sred[wi];
        unsigned long long qv = (unsigned long long)__double2ll_rn(s * 4294967296.0);
        atomicAdd(&g_loss_acc, qv);
        __threadfence();
        unsigned tick = atomicAdd(&g_tick, 1u);
        if (tick == K3_BLOCKS - 1) {
            unsigned long long acc = atomicAdd(&g_loss_acc, 0ULL);
            out[BP*4] = (float)((double)acc * (1.0/4294967296.0) / (double)B);
        }
    }
}

// ============================================================
extern "C" void kernel_launch(void* const* d_in, const int* in_sizes, int n_in,
                              void* d_out, int out_size)
{
    const float* inputs    = (const float*)d_in[0];
    const float* pre_score = (const float*)d_in[1];
    const float* labels    = (const float*)d_in[2];
    const float* rois      = (const float*)d_in[3];
    const float* fcw       = (const float*)d_in[4];
    const float* fcb       = (const float*)d_in[5];
    float* out = (float*)d_out;

    const int K2_SMEM = P * 32;   // 64 KB
    cudaFuncSetAttribute(k2_scan, cudaFuncAttributeMaxDynamicSharedMemorySize, K2_SMEM);

    k0_build<<<B, 256>>>(rois, pre_score);
    k2_scan<<<B*16, 128, K2_SMEM>>>(pre_score, labels);
    k3_loss<<<K3_BLOCKS, 256>>>(inputs, labels, fcw, fcb, out);
}